// round 3
// baseline (speedup 1.0000x reference)
#include <cuda_runtime.h>
#include <math.h>

#define TPB 256
#define NWARP (TPB / 32)
#define BUFCAP 4096
#define MAXB 2048
#define SLICE 2048            // elements per slice block (multiple of 8*TPB/..., and of 4)
#define MAXS 64               // max slices per row -> rows up to 131072 elems on fast path

__device__ float g_rowloss[MAXB];
__device__ unsigned g_done;                 // zero-init; reset by last block each launch
__device__ float g_wbuf[MAXB][BUFCAP];      // per-row window candidates
__device__ int   g_widx[MAXB];              // per-row window fill count (reset by kernel 2)
__device__ int   g_ovf[MAXB];               // per-row overflow flag   (reset by kernel 2)
__device__ int   g_scU[MAXB * MAXS];        // per-slice count(>U)
__device__ int   g_scL[MAXB * MAXS];        // per-slice count(>L)
__device__ float g_ssU[MAXB * MAXS];        // per-slice sum(>U)

__device__ __forceinline__ float warpRedF(float v) {
#pragma unroll
    for (int o = 16; o > 0; o >>= 1) v += __shfl_down_sync(0xffffffffu, v, o);
    return v;
}
__device__ __forceinline__ int warpRedI(int v) {
#pragma unroll
    for (int o = 16; o > 0; o >>= 1) v += __shfl_down_sync(0xffffffffu, v, o);
    return v;
}

// per-row statistical window around the k-th order-statistic quantile
__device__ __forceinline__ void row_window(int n, int k, float& L, float& U) {
    float fn = (float)n, fk = (float)k;
    float mean = 1.0f - fk / fn;
    float sig  = sqrtf(fk) / fn;            // >= Beta std -> conservative
    L = fmaxf(0.0f, mean - 10.0f * sig);
    U = fminf(1.0f, mean + 10.0f * sig);
}

// ---------------- Kernel 1: flat slice pass (perfectly parallel) ----------------
__global__ __launch_bounds__(TPB) void slice_kernel(
    const float* __restrict__ scores,
    const int* __restrict__ seqlen,
    int T, int S)
{
    __shared__ float s_sl[SLICE];
    __shared__ int   s_w;
    __shared__ float s_rf[NWARP];
    __shared__ int   s_ri[NWARP];
    __shared__ int   s_ri2[NWARP];
    __shared__ int   s_base;

    const int gid  = blockIdx.x;
    const int row  = gid / S;
    const int sl   = gid - row * S;
    const int tid  = threadIdx.x;
    const int lane = tid & 31;
    const int wid  = tid >> 5;

    const int n = seqlen[row];
    if (n <= BUFCAP) return;                 // small rows handled entirely by kernel 2
    const int start = sl * SLICE;
    if (start >= n) return;
    const int end = min(start + SLICE, n);

    const int k = (n >> 4) + 1;
    float L, U;
    row_window(n, k, L, U);

    if (tid == 0) s_w = 0;
    __syncthreads();

    const float4* rp4 = (const float4*)(scores + (size_t)row * (size_t)T);
    const int i40 = start >> 2;
    const int i41 = end >> 2;                // full float4s in this slice

    int   cU = 0, cL = 0;
    float sU = 0.0f;

    for (int i = i40 + tid; i < i41; i += TPB) {
        float4 v4 = rp4[i];
        float xs[4] = {v4.x, v4.y, v4.z, v4.w};
#pragma unroll
        for (int c = 0; c < 4; ++c) {
            float x = xs[c];
            bool gtU = x > U;
            bool gtL = x > L;
            cL += gtL;
            if (gtU) { cU++; sU += x; }
            else if (gtL) {
                int p = atomicAdd(&s_w, 1);  // p < SLICE by construction
                s_sl[p] = x;
            }
        }
    }
    {   // scalar tail (only on the row's final slice when n % 4 != 0)
        int t = (i41 << 2) + tid;
        if (t < end) {
            float x = (scores + (size_t)row * (size_t)T)[t];
            bool gtU = x > U;
            bool gtL = x > L;
            cL += gtL;
            if (gtU) { cU++; sU += x; }
            else if (gtL) {
                int p = atomicAdd(&s_w, 1);
                s_sl[p] = x;
            }
        }
    }

    cU = warpRedI(cU); cL = warpRedI(cL); sU = warpRedF(sU);
    if (lane == 0) { s_ri[wid] = cU; s_ri2[wid] = cL; s_rf[wid] = sU; }
    __syncthreads();

    if (tid == 0) {
        int CU = 0, CL = 0; float SU = 0.0f;
        for (int j = 0; j < NWARP; ++j) { CU += s_ri[j]; CL += s_ri2[j]; SU += s_rf[j]; }
        g_scU[row * MAXS + sl] = CU;
        g_scL[row * MAXS + sl] = CL;
        g_ssU[row * MAXS + sl] = SU;
        int cnt  = s_w;
        int base = (cnt > 0) ? atomicAdd(&g_widx[row], cnt) : 0;
        if (base + cnt > BUFCAP) g_ovf[row] = 1;
        s_base = base;
    }
    __syncthreads();

    const int cnt = s_w, base = s_base;
    for (int i = tid; i < cnt; i += TPB) {
        int d = base + i;
        if (d < BUFCAP) g_wbuf[row][d] = s_sl[i];
    }
}

// ---------------- Kernel 2: per-row finish (select + loss + reduction) ----------------
__global__ __launch_bounds__(TPB) void finish_kernel(
    const float* __restrict__ scores,
    const float* __restrict__ label,
    const int* __restrict__ seqlen,
    int T, int B, int S,
    float* __restrict__ out)
{
    __shared__ float s_buf[BUFCAP];
    __shared__ int   s_hist[256];
    __shared__ float s_rf[NWARP];
    __shared__ int   s_ri[NWARP];
    __shared__ int   s_ri2[NWARP];
    __shared__ int   s_widx;
    __shared__ float s_Lb, s_Ub;
    __shared__ int   s_status;   // 1 = select in buffer, 2 = tie (thr known exactly)
    __shared__ int   s_m;
    __shared__ int   s_cntU;
    __shared__ float s_sumU;
    __shared__ unsigned s_prefix;
    __shared__ int   s_kk;
    __shared__ float s_thr;
    __shared__ int   s_last;

    const int row  = blockIdx.x;
    const int tid  = threadIdx.x;
    const int lane = tid & 31;
    const int wid  = tid >> 5;

    const int n = seqlen[row];
    const int k = (n >> 4) + 1;
    const float* rp = scores + (size_t)row * (size_t)T;

    bool fastok = false;

    if (n <= BUFCAP) {
        for (int i = tid; i < n; i += TPB) s_buf[i] = rp[i];
        if (tid == 0) { s_status = 1; s_m = n; s_cntU = 0; s_sumU = 0.0f; s_thr = 0.5f; }
        __syncthreads();
        fastok = true;
    } else if (S > 0) {
        // aggregate per-slice results in deterministic fixed-tree order
        const int Sact = min((n + SLICE - 1) / SLICE, S);
        int   cU = 0, cL = 0;
        float sU = 0.0f;
        if (tid < Sact) {
            cU = g_scU[row * MAXS + tid];
            cL = g_scL[row * MAXS + tid];
            sU = g_ssU[row * MAXS + tid];
        }
        cU = warpRedI(cU); cL = warpRedI(cL); sU = warpRedF(sU);
        if (lane == 0) { s_ri[wid] = cU; s_ri2[wid] = cL; s_rf[wid] = sU; }
        __syncthreads();
        if (tid == 0) {
            int CU = 0, CL = 0; float SU = 0.0f;
            for (int j = 0; j < NWARP; ++j) { CU += s_ri[j]; CL += s_ri2[j]; SU += s_rf[j]; }
            int m = CL - CU;
            int ok = (!g_ovf[row]) && (CU < k) && (CL >= k) && (m <= BUFCAP);
            s_status = ok ? 1 : 0;
            s_m = m; s_cntU = CU; s_sumU = SU; s_thr = 0.5f;
        }
        __syncthreads();
        if (s_status == 1) {
            const int m = s_m;
            for (int i = tid; i < m; i += TPB) s_buf[i] = g_wbuf[row][i];
            __syncthreads();
            fastok = true;
        }
    }

    if (!fastok) {
        // ---------- deterministic fallback: full bisection over the row ----------
        float gL = 0.0f, gU = 1.0f;
        bool  tiemode = false;
        if (tid == 0) {
            float L, U; row_window(n, k, L, U);
            s_Lb = L; s_Ub = U;
            s_status = 0; s_m = 0; s_thr = 0.5f; s_cntU = 0; s_sumU = 0.0f;
        }
        const float4* rp4 = (const float4*)rp;
        const int nv   = n >> 2;
        const int STEP = TPB * 2;
        const int nvr  = ((nv + STEP - 1) / STEP) * STEP;

        for (int iter = 0; iter < 64; ++iter) {
            __syncthreads();
            const float L = s_Lb, U = s_Ub;
            if (tid == 0) s_widx = 0;
            __syncthreads();

            int cU = 0, cL = 0; float sU = 0.0f;
            for (int base = tid; base < nvr; base += STEP) {
                const int i1 = base + TPB;
                float4 a = (base < nv) ? rp4[base] : make_float4(-1.f,-1.f,-1.f,-1.f);
                float4 b = (i1   < nv) ? rp4[i1]   : make_float4(-1.f,-1.f,-1.f,-1.f);
                float xs[8] = {a.x,a.y,a.z,a.w,b.x,b.y,b.z,b.w};
#pragma unroll
                for (int c = 0; c < 8; ++c) {
                    float x = xs[c];
                    bool gtU = x > U;
                    bool gtL = x > L;
                    cL += gtL;
                    if (gtU) { cU++; sU += x; }
                    else if (gtL) {
                        int p = atomicAdd(&s_widx, 1);
                        if (p < BUFCAP) s_buf[p] = x;
                    }
                }
            }
            {
                int i = (nv << 2) + tid;
                if (i < n) {
                    float x = rp[i];
                    bool gtU = x > U;
                    bool gtL = x > L;
                    cL += gtL;
                    if (gtU) { cU++; sU += x; }
                    else if (gtL) {
                        int p = atomicAdd(&s_widx, 1);
                        if (p < BUFCAP) s_buf[p] = x;
                    }
                }
            }

            cU = warpRedI(cU); cL = warpRedI(cL); sU = warpRedF(sU);
            if (lane == 0) { s_ri[wid] = cU; s_ri2[wid] = cL; s_rf[wid] = sU; }
            __syncthreads();

            if (tid == 0) {
                int CU = 0, CL = 0; float SU = 0.0f;
                for (int j = 0; j < NWARP; ++j) { CU += s_ri[j]; CL += s_ri2[j]; SU += s_rf[j]; }
                if (tiemode) {
                    s_status = 2; s_cntU = CU; s_sumU = SU; s_m = 0; s_thr = U;
                } else {
                    bool done = false;
                    if (CU < k && CL >= k) {
                        int mm = CL - CU;
                        if (mm <= BUFCAP) {
                            s_status = 1; s_cntU = CU; s_sumU = SU; s_m = mm;
                            done = true;
                        } else { gL = L; gU = U; }
                    } else if (CU >= k) {
                        gL = U;
                    } else {
                        gU = L;
                    }
                    if (!done) {
                        if (__float_as_uint(gU) - __float_as_uint(gL) <= 1u) {
                            tiemode = true; s_Lb = gU; s_Ub = gU;
                        } else {
                            float mid = 0.5f * (gL + gU);
                            if (!(mid > gL && mid < gU))
                                mid = __uint_as_float((__float_as_uint(gL) + __float_as_uint(gU)) >> 1);
                            s_Lb = gL; s_Ub = mid;
                        }
                    }
                }
            }
            __syncthreads();
            if (s_status != 0) break;
        }
        __syncthreads();
    }

    const int st = s_status;
    const int m  = s_m;

    if (st == 1) {
        // exact 8-bit radix select: (k - cntU)-th largest among m positive floats
        if (tid == 0) { s_prefix = 0u; s_kk = k - s_cntU; }
        for (int pos = 24; pos >= 0; pos -= 8) {
            __syncthreads();
            for (int j = tid; j < 256; j += TPB) s_hist[j] = 0;
            __syncthreads();
            const unsigned pref  = s_prefix;
            const unsigned pmask = (pos == 24) ? 0u : (0xffffffffu << (pos + 8));
            for (int i = tid; i < m; i += TPB) {
                unsigned v = __float_as_uint(s_buf[i]);
                if ((v & pmask) == pref)
                    atomicAdd(&s_hist[(v >> pos) & 255], 1);
            }
            __syncthreads();
            if (tid == 0) {
                int kk = s_kk;
                int c = 0, d = 255;
                for (; d >= 0; --d) { c += s_hist[d]; if (c >= kk) break; }
                if (d < 0) d = 0;
                s_kk = kk - (c - s_hist[d]);
                s_prefix = pref | ((unsigned)d << (unsigned)pos);
            }
        }
        __syncthreads();
        if (tid == 0) s_thr = __uint_as_float(s_prefix);
        __syncthreads();
    }

    // exact tie-corrected top-k sum
    const float thr = s_thr;
    float sg = 0.0f; int cg = 0;
    for (int i = tid; i < m; i += TPB) {
        float x = s_buf[i];
        if (x > thr) { sg += x; cg++; }
    }
    sg = warpRedF(sg); cg = warpRedI(cg);
    if (lane == 0) { s_rf[wid] = sg; s_ri[wid] = cg; }
    __syncthreads();
    if (tid == 0) {
        float SG = 0.0f; int CG = 0;
        for (int j = 0; j < NWARP; ++j) { SG += s_rf[j]; CG += s_ri[j]; }
        float topk = s_sumU + SG + (float)(k - s_cntU - CG) * thr;
        float vl   = topk / (float)k;
        float lab  = label[row];
        g_rowloss[row] = -(lab * logf(vl) + (1.0f - lab) * log1pf(-vl));
        g_widx[row] = 0;                    // reset scratch for next graph replay
        g_ovf[row]  = 0;
    }

    // last-block-done: final scalar reduction
    __threadfence();
    if (tid == 0) {
        unsigned t = atomicAdd(&g_done, 1u);
        s_last = (t == (unsigned)(gridDim.x - 1));
    }
    __syncthreads();
    if (s_last) {
        __threadfence();
        float v = 0.0f;
        for (int i = tid; i < B; i += TPB) v += g_rowloss[i];
        v = warpRedF(v);
        if (lane == 0) s_rf[wid] = v;
        __syncthreads();
        if (tid == 0) {
            float t = 0.0f;
            for (int j = 0; j < NWARP; ++j) t += s_rf[j];
            out[0] = t / (float)B;
            g_done = 0;
        }
    }
}

extern "C" void kernel_launch(void* const* d_in, const int* in_sizes, int n_in,
                              void* d_out, int out_size) {
    const float* scores = (const float*)d_in[0];
    const float* label  = (const float*)d_in[1];
    const int*   seqlen = (const int*)d_in[2];
    int B = in_sizes[1];
    if (B > MAXB) B = MAXB;
    int T = in_sizes[0] / B;

    int S = (T + SLICE - 1) / SLICE;
    if (S > MAXS) S = 0;                    // rows too long for fast path -> kernel 2 fallback

    if (S > 0)
        slice_kernel<<<B * S, TPB>>>(scores, seqlen, T, S);
    finish_kernel<<<B, TPB>>>(scores, label, seqlen, T, B, S, (float*)d_out);
}

// round 4
// speedup vs baseline: 1.5342x; 1.5342x over previous
#include <cuda_runtime.h>
#include <math.h>

#define TPB 256
#define NWARP 8
#define CHUNK 8192            // elements per slice block
#define MAXS 8                // max slices per row
#define CANDCAP 2048          // SMEM candidate buffer (per block / per row select)
#define BUFCAP 4096           // global per-row candidate buffer
#define NB 512                // select buckets
#define NCO (NB / 16)         // coarse bins
#define BBCAP 64              // boundary-bucket capacity for exact rank select
#define FULLCAP 2048          // rows with n <= FULLCAP are captured whole
#define MAXB 2048

__device__ float    g_rowloss[MAXB];
__device__ unsigned g_done;                  // zero-init; reset each launch by last block
__device__ float    g_wbuf[MAXB][BUFCAP];    // per-row window candidates
__device__ int      g_widx[MAXB];            // per-row candidate count   (reset by finisher)
__device__ int      g_ovf[MAXB];             // per-row overflow flag     (reset by finisher)
__device__ int      g_rowdone[MAXB];         // per-row slice-done count  (reset by finisher)
__device__ int      g_scU[MAXB * MAXS];      // per-slice count(>U)
__device__ float    g_ssU[MAXB * MAXS];      // per-slice sum(>U)

__device__ __forceinline__ float warpRedF(float v) {
#pragma unroll
    for (int o = 16; o > 0; o >>= 1) v += __shfl_down_sync(0xffffffffu, v, o);
    return v;
}
__device__ __forceinline__ int warpRedI(int v) {
#pragma unroll
    for (int o = 16; o > 0; o >>= 1) v += __shfl_down_sync(0xffffffffu, v, o);
    return v;
}

// statistical window around the k-th order-statistic quantile (uniform scores)
__device__ __forceinline__ void row_window(int n, int k, float& L, float& U) {
    float fn = (float)n, fk = (float)k;
    float mean = 1.0f - fk / fn;
    float sig  = sqrtf(fk) / fn;          // >= Beta std -> conservative
    L = fmaxf(0.0f, mean - 10.0f * sig);
    U = fminf(1.0f, mean + 10.0f * sig);
}

__global__ __launch_bounds__(TPB, 6) void fused_kernel(
    const float* __restrict__ scores,
    const float* __restrict__ label,
    const int*   __restrict__ seqlen,
    int T, int B, int S, int chunkLen,
    float* __restrict__ out)
{
    __shared__ float s_cand[CANDCAP];
    __shared__ int   s_hist[NB];
    __shared__ int   s_coarse[NCO];
    __shared__ float s_bb[BBCAP];
    __shared__ int   s_rank[BBCAP];
    __shared__ float s_rf[NWARP];
    __shared__ float s_rf2[NWARP];
    __shared__ int   s_ri[NWARP];
    __shared__ int   s_ri2[NWARP];
    __shared__ int   s_nc, s_base, s_isfin, s_lastB, s_donef;
    __shared__ int   s_CU, s_m, s_ok, s_b, s_above, s_nb;
    __shared__ float s_SU, s_thr;
    __shared__ float s_Lb, s_Ub;
    __shared__ int   s_status;
    __shared__ unsigned s_prefix;
    __shared__ int   s_kk;

    const int gid  = blockIdx.x;
    const int row  = gid / S;
    const int sl   = gid - row * S;
    const int tid  = threadIdx.x;
    const int lane = tid & 31;
    const int wid  = tid >> 5;

    const int n = seqlen[row];
    const int c0 = sl * chunkLen;
    if (c0 >= n) return;                          // inactive slice
    const int Sact = (n + chunkLen - 1) / chunkLen;
    const int k = (n >> 4) + 1;                   // seqlen//16 + 1
    const bool fullcap = (n <= FULLCAP);

    float L, U;
    if (fullcap) { L = -2.0f; U = 2.0f; }         // capture everything
    else row_window(n, k, L, U);

    const float* rp = scores + (size_t)row * (size_t)T;
    const float4* rp4 = (const float4*)rp;

    if (tid == 0) s_nc = 0;
    __syncthreads();

    // ---------------- streaming over this chunk, MLP=4 batched float4 ----------------
    const int c1 = min(c0 + chunkLen, n);
    const int f0 = c0 >> 2, f1 = c1 >> 2;

    int   cU = 0;
    float sU = 0.0f;

    for (int b0 = f0; b0 < f1; b0 += 4 * TPB) {
        float4 v[4];
#pragma unroll
        for (int j = 0; j < 4; ++j) {
            int idx = b0 + tid + j * TPB;
            v[j] = (idx < f1) ? rp4[idx] : make_float4(-9.f, -9.f, -9.f, -9.f);
        }
#pragma unroll
        for (int j = 0; j < 4; ++j) {
            float xs[4] = {v[j].x, v[j].y, v[j].z, v[j].w};
#pragma unroll
            for (int c = 0; c < 4; ++c) {
                float x = xs[c];
                if (x > U) { cU++; sU += x; }
                else if (x > L) {
                    int p = atomicAdd(&s_nc, 1);
                    if (p < CANDCAP) s_cand[p] = x;
                }
            }
        }
    }
    {   // scalar tail (< 4 elements, only on the row's last chunk)
        int tb = f1 << 2;
        if (tb + tid < c1) {
            float x = rp[tb + tid];
            if (x > U) { cU++; sU += x; }
            else if (x > L) {
                int p = atomicAdd(&s_nc, 1);
                if (p < CANDCAP) s_cand[p] = x;
            }
        }
    }

    cU = warpRedI(cU); sU = warpRedF(sU);
    if (lane == 0) { s_ri[wid] = cU; s_rf[wid] = sU; }
    __syncthreads();

    if (tid == 0) {
        int CU = 0; float SU = 0.0f;
        for (int j = 0; j < NWARP; ++j) { CU += s_ri[j]; SU += s_rf[j]; }
        g_scU[row * MAXS + sl] = CU;
        g_ssU[row * MAXS + sl] = SU;
        int cnt = s_nc;
        int base = 0;
        if (Sact > 1 && cnt > 0) base = atomicAdd(&g_widx[row], cnt);
        if (cnt > CANDCAP || base + cnt > BUFCAP) g_ovf[row] = 1;
        s_base = base;
    }
    __syncthreads();

    if (Sact > 1) {
        const int cnt = min(s_nc, CANDCAP), base = s_base;
        for (int i = tid; i < cnt; i += TPB) {
            int d = base + i;
            if (d < BUFCAP) g_wbuf[row][d] = s_cand[i];
        }
    }
    __threadfence();
    __syncthreads();
    if (tid == 0) s_isfin = (atomicAdd(&g_rowdone[row], 1) == Sact - 1) ? 1 : 0;
    __syncthreads();
    if (!s_isfin) return;

    // ================= finisher: this block completes the row =================
    __threadfence();

    if (tid == 0) {
        int CU = 0; float SU = 0.0f;
        for (int j = 0; j < Sact; ++j) { CU += g_scU[row * MAXS + j]; SU += g_ssU[row * MAXS + j]; }
        int m = (Sact == 1) ? s_nc : g_widx[row];
        int ok = (!g_ovf[row]) && (m <= CANDCAP) &&
                 (fullcap ? 1 : (CU < k && CU + m >= k));
        s_CU = CU; s_SU = SU; s_m = m; s_ok = ok;
        s_donef = 0; s_thr = 0.5f; s_status = 1;
    }
    __syncthreads();

    const int ok = s_ok;
    if (ok && Sact > 1) {
        const int m = s_m;
        for (int i = tid; i < m; i += TPB) s_cand[i] = g_wbuf[row][i];
        __syncthreads();
    }

    // ---------------- fast path: 1-pass bucket select ----------------
    if (ok) {
        const int   m  = s_m;
        const int   kk = k - s_CU;
        const float Ls = fullcap ? 0.0f : L;
        const float Us = fullcap ? 1.0f : U;
        const float scale = (float)NB / (Us - Ls);

        for (int j = tid; j < NB; j += TPB) s_hist[j] = 0;
        __syncthreads();
        for (int i = tid; i < m; i += TPB) {
            float x = s_cand[i];
            int bi = (int)((Us - x) * scale);
            bi = bi < 0 ? 0 : (bi > NB - 1 ? NB - 1 : bi);
            atomicAdd(&s_hist[bi], 1);
        }
        __syncthreads();
        if (tid < NCO) {
            int t = 0;
            for (int j = 0; j < 16; ++j) t += s_hist[tid * 16 + j];
            s_coarse[tid] = t;
        }
        __syncthreads();
        if (tid == 0) {
            int cum = 0, cb = 0;
            while (cb < NCO - 1 && cum + s_coarse[cb] < kk) { cum += s_coarse[cb]; ++cb; }
            int b = cb * 16;
            while (b < NB - 1 && cum + s_hist[b] < kk) { cum += s_hist[b]; ++b; }
            s_b = b; s_above = cum; s_nb = 0;
        }
        __syncthreads();

        const int b = s_b;
        float sa = 0.0f;
        for (int i = tid; i < m; i += TPB) {
            float x = s_cand[i];
            int bi = (int)((Us - x) * scale);
            bi = bi < 0 ? 0 : (bi > NB - 1 ? NB - 1 : bi);
            if (bi < b) sa += x;
            else if (bi == b) {
                int p = atomicAdd(&s_nb, 1);
                if (p < BBCAP) s_bb[p] = x;
            }
        }
        sa = warpRedF(sa);
        if (lane == 0) s_rf[wid] = sa;
        __syncthreads();

        const int nb = s_nb;
        if (nb <= BBCAP) {
            const int kk2 = kk - s_above;            // 1..nb by construction
            if (tid < nb) {
                float xv = s_bb[tid]; int r = 0;
                for (int j = 0; j < nb; ++j) {
                    float y = s_bb[j];
                    r += (y > xv) || (y == xv && j < tid);   // exact tie-broken rank
                }
                s_rank[tid] = r;
            }
            __syncthreads();
            float c = (tid < nb && s_rank[tid] < kk2) ? s_bb[tid] : 0.0f;
            c = warpRedF(c);
            if (lane == 0) s_rf2[wid] = c;
            __syncthreads();
            if (tid == 0) {
                float SA = 0.0f, SS = 0.0f;
                for (int j = 0; j < NWARP; ++j) { SA += s_rf[j]; SS += s_rf2[j]; }
                float topk = s_SU + SA + SS;         // exactly k elements summed
                float vl   = topk / (float)k;
                float lab  = label[row];
                g_rowloss[row] = -(lab * logf(vl) + (1.0f - lab) * log1pf(-vl));
                s_donef = 1;
            }
            __syncthreads();
        }
        // nb > BBCAP (heavy ties): fall through to radix path on s_cand below
    }

    if (!s_donef) {
        if (!ok) {
            // ---------- deterministic fallback: full-row bisection ----------
            float gL = 0.0f, gU = 1.0f;
            bool  tiemode = false;
            if (tid == 0) {
                float Lw, Uw; row_window(n, k, Lw, Uw);
                s_Lb = fullcap ? 0.0f : Lw;
                s_Ub = fullcap ? 1.0f : Uw;
                s_status = 0; s_m = 0; s_thr = 0.5f; s_CU = 0; s_SU = 0.0f;
            }
            const int nv   = n >> 2;
            const int STEP = TPB * 2;
            const int nvr  = ((nv + STEP - 1) / STEP) * STEP;

            for (int iter = 0; iter < 64; ++iter) {
                __syncthreads();
                const float Lb = s_Lb, Ub = s_Ub;
                if (tid == 0) s_nc = 0;
                __syncthreads();

                int cu = 0, cl = 0; float su = 0.0f;
                for (int base = tid; base < nvr; base += STEP) {
                    const int i1 = base + TPB;
                    float4 a = (base < nv) ? rp4[base] : make_float4(-9.f,-9.f,-9.f,-9.f);
                    float4 bq = (i1  < nv) ? rp4[i1]   : make_float4(-9.f,-9.f,-9.f,-9.f);
                    float xs[8] = {a.x,a.y,a.z,a.w,bq.x,bq.y,bq.z,bq.w};
#pragma unroll
                    for (int c = 0; c < 8; ++c) {
                        float x = xs[c];
                        bool gtU = x > Ub, gtL = x > Lb;
                        cl += gtL;
                        if (gtU) { cu++; su += x; }
                        else if (gtL) {
                            int p = atomicAdd(&s_nc, 1);
                            if (p < CANDCAP) s_cand[p] = x;
                        }
                    }
                }
                {
                    int i = (nv << 2) + tid;
                    if (i < n) {
                        float x = rp[i];
                        bool gtU = x > Ub, gtL = x > Lb;
                        cl += gtL;
                        if (gtU) { cu++; su += x; }
                        else if (gtL) {
                            int p = atomicAdd(&s_nc, 1);
                            if (p < CANDCAP) s_cand[p] = x;
                        }
                    }
                }
                cu = warpRedI(cu); cl = warpRedI(cl); su = warpRedF(su);
                if (lane == 0) { s_ri[wid] = cu; s_ri2[wid] = cl; s_rf[wid] = su; }
                __syncthreads();

                if (tid == 0) {
                    int CU = 0, CL = 0; float SU = 0.0f;
                    for (int j = 0; j < NWARP; ++j) { CU += s_ri[j]; CL += s_ri2[j]; SU += s_rf[j]; }
                    if (tiemode) {
                        s_status = 2; s_CU = CU; s_SU = SU; s_m = 0; s_thr = Ub;
                    } else {
                        bool done = false;
                        if (CU < k && CL >= k) {
                            int mm = CL - CU;
                            if (mm <= CANDCAP) {
                                s_status = 1; s_CU = CU; s_SU = SU; s_m = mm;
                                done = true;
                            } else { gL = Lb; gU = Ub; }
                        } else if (CU >= k) {
                            gL = Ub;
                        } else {
                            gU = Lb;
                        }
                        if (!done) {
                            if (__float_as_uint(gU) - __float_as_uint(gL) <= 1u) {
                                tiemode = true; s_Lb = gU; s_Ub = gU;
                            } else {
                                float mid = 0.5f * (gL + gU);
                                if (!(mid > gL && mid < gU))
                                    mid = __uint_as_float((__float_as_uint(gL) + __float_as_uint(gU)) >> 1);
                                s_Lb = gL; s_Ub = mid;
                            }
                        }
                    }
                }
                __syncthreads();
                if (s_status != 0) break;
            }
            __syncthreads();
        }

        const int st = s_status;
        const int m  = s_m;

        if (st == 1) {
            // exact 8-bit radix select among m positive floats in s_cand
            if (tid == 0) { s_prefix = 0u; s_kk = k - s_CU; }
            for (int pos = 24; pos >= 0; pos -= 8) {
                __syncthreads();
                for (int j = tid; j < 256; j += TPB) s_hist[j] = 0;
                __syncthreads();
                const unsigned pref  = s_prefix;
                const unsigned pmask = (pos == 24) ? 0u : (0xffffffffu << (pos + 8));
                for (int i = tid; i < m; i += TPB) {
                    unsigned v = __float_as_uint(s_cand[i]);
                    if ((v & pmask) == pref)
                        atomicAdd(&s_hist[(v >> pos) & 255], 1);
                }
                __syncthreads();
                if (tid == 0) {
                    int kk = s_kk;
                    int c = 0, d = 255;
                    for (; d >= 0; --d) { c += s_hist[d]; if (c >= kk) break; }
                    if (d < 0) d = 0;
                    s_kk = kk - (c - s_hist[d]);
                    s_prefix = pref | ((unsigned)d << (unsigned)pos);
                }
            }
            __syncthreads();
            if (tid == 0) s_thr = __uint_as_float(s_prefix);
            __syncthreads();
        }

        // tie-corrected top-k sum with threshold
        const float thr = s_thr;
        float sg = 0.0f; int cg = 0;
        for (int i = tid; i < m; i += TPB) {
            float x = s_cand[i];
            if (x > thr) { sg += x; cg++; }
        }
        sg = warpRedF(sg); cg = warpRedI(cg);
        if (lane == 0) { s_rf[wid] = sg; s_ri[wid] = cg; }
        __syncthreads();
        if (tid == 0) {
            float SG = 0.0f; int CG = 0;
            for (int j = 0; j < NWARP; ++j) { SG += s_rf[j]; CG += s_ri[j]; }
            float topk = s_SU + SG + (float)(k - s_CU - CG) * thr;
            float vl   = topk / (float)k;
            float lab  = label[row];
            g_rowloss[row] = -(lab * logf(vl) + (1.0f - lab) * log1pf(-vl));
        }
        __syncthreads();
    }

    // reset per-row scratch for the next graph replay
    if (tid == 0) { g_widx[row] = 0; g_ovf[row] = 0; g_rowdone[row] = 0; }
    __threadfence();
    __syncthreads();
    if (tid == 0) s_lastB = (atomicAdd(&g_done, 1u) == (unsigned)(B - 1)) ? 1 : 0;
    __syncthreads();
    if (s_lastB) {
        __threadfence();
        float v = 0.0f;
        for (int i = tid; i < B; i += TPB) v += g_rowloss[i];
        v = warpRedF(v);
        if (lane == 0) s_rf[wid] = v;
        __syncthreads();
        if (tid == 0) {
            float t = 0.0f;
            for (int j = 0; j < NWARP; ++j) t += s_rf[j];
            out[0] = t / (float)B;
            g_done = 0;
        }
    }
}

extern "C" void kernel_launch(void* const* d_in, const int* in_sizes, int n_in,
                              void* d_out, int out_size) {
    const float* scores = (const float*)d_in[0];
    const float* label  = (const float*)d_in[1];
    const int*   seqlen = (const int*)d_in[2];
    int B = in_sizes[1];
    if (B > MAXB) B = MAXB;
    int T = in_sizes[0] / B;

    int S = (T + CHUNK - 1) / CHUNK;
    if (S < 1) S = 1;
    if (S > MAXS) S = MAXS;
    int chunkLen = (((T + S - 1) / S) + 3) & ~3;

    fused_kernel<<<B * S, TPB>>>(scores, label, seqlen, T, B, S, chunkLen, (float*)d_out);
}

// round 5
// speedup vs baseline: 1.6134x; 1.0517x over previous
#include <cuda_runtime.h>
#include <math.h>

#define TPB 256
#define NWARP 8
#define WCAP 512               // per-warp stage capacity = chunk share (4096/8)
#define SELCAP 4096            // NWARP*WCAP; stage buffer reused as select buffer
#define BUFCAP 4096            // global per-row candidate buffer
#define CHUNK 4096             // elements per slice block
#define NB 512                 // select buckets
#define NCO 32                 // coarse bins (NB/16)
#define BBCAP 64               // boundary-bucket capacity
#define MAXB 2048
#define MAXS 16
#define SMALLN 2048            // rows this short are captured whole (tau = -1)

__device__ float    g_rowloss[MAXB];
__device__ unsigned g_done;                 // zero-init; reset by last block each launch
__device__ float    g_wbuf[MAXB][BUFCAP];   // per-row candidates (> tau)
__device__ int      g_widx[MAXB];           // per-row candidate count (reset by finisher)
__device__ int      g_ovf[MAXB];            // per-row overflow flag   (reset by finisher)
__device__ int      g_rowdone[MAXB];        // per-row slice-done count (reset by finisher)

__device__ __forceinline__ float warpRedF(float v) {
#pragma unroll
    for (int o = 16; o > 0; o >>= 1) v += __shfl_down_sync(0xffffffffu, v, o);
    return v;
}
__device__ __forceinline__ int warpRedI(int v) {
#pragma unroll
    for (int o = 16; o > 0; o >>= 1) v += __shfl_down_sync(0xffffffffu, v, o);
    return v;
}

// single capture threshold: below the k-th order statistic whp (uniform scores)
__device__ __forceinline__ float row_tau(int n, int k) {
    if (n <= SMALLN) return -1.0f;          // capture everything
    float fn = (float)n, fk = (float)k;
    return fmaxf(0.0f, 1.0f - fk / fn - 10.0f * sqrtf(fk) / fn);
}

__global__ __launch_bounds__(TPB) void fused_kernel(
    const float* __restrict__ scores,
    const float* __restrict__ label,
    const int*   __restrict__ seqlen,
    int T, int B, int S, int chunkLen,
    float* __restrict__ out)
{
    __shared__ float s_sel[SELCAP];          // stage (8 x WCAP) then select buffer
    __shared__ int   s_hist[NB];
    __shared__ int   s_coarse[NCO];
    __shared__ float s_bb[BBCAP];
    __shared__ int   s_rank[BBCAP];
    __shared__ float s_rf[NWARP], s_rf2[NWARP];
    __shared__ int   s_ri[NWARP], s_ri2[NWARP];
    __shared__ int   s_wc[NWARP], s_pre[NWARP];
    __shared__ int   s_gbase, s_isfin, s_lastB, s_donef;
    __shared__ int   s_m, s_ok, s_b, s_above, s_nb, s_nc;
    __shared__ float s_thr, s_Lb, s_Ub, s_SU;
    __shared__ int   s_status, s_kk, s_CU;
    __shared__ unsigned s_prefix;

    const int gid  = blockIdx.x;
    const int row  = gid / S;
    const int sl   = gid - row * S;
    const int tid  = threadIdx.x;
    const int lane = tid & 31;
    const int wid  = tid >> 5;

    const int n  = seqlen[row];
    const int c0 = sl * chunkLen;
    if (c0 >= n) return;                     // inactive slice
    const int Sact = (n + chunkLen - 1) / chunkLen;
    const int k    = (n >> 4) + 1;           // seqlen//16 + 1
    const float tau = row_tau(n, k);

    const float* rp = scores + (size_t)row * (size_t)T;
    const int c1 = min(c0 + chunkLen, n);
    const unsigned lmlt = (1u << lane) - 1u;
    float* wstage = s_sel + wid * WCAP;
    int wcnt = 0;

    // ---------------- stream: atomic-free ballot compaction of x > tau ----------------
    if ((T & 3) == 0) {
        const float4* rp4 = (const float4*)rp;
        const int q0 = c0 >> 2, q1 = c1 >> 2;
        int base = q0;
        // unguarded full groups: 4 independent LDG.128 per thread, no selects
        for (; base + 4 * TPB <= q1; base += 4 * TPB) {
            float4 v[4];
#pragma unroll
            for (int j = 0; j < 4; ++j) v[j] = rp4[base + tid + j * TPB];
#pragma unroll
            for (int j = 0; j < 4; ++j) {
                float xs[4] = {v[j].x, v[j].y, v[j].z, v[j].w};
#pragma unroll
                for (int c = 0; c < 4; ++c) {
                    float x = xs[c];
                    bool q = x > tau;
                    unsigned msk = __ballot_sync(0xffffffffu, q);
                    int off = wcnt + __popc(msk & lmlt);
                    if (q && off < WCAP) wstage[off] = x;
                    wcnt += __popc(msk);
                }
            }
        }
        // guarded remainder group + scalar tail (block-uniform condition)
        if (base < q1 || (q1 << 2) < c1) {
            float4 v[4];
#pragma unroll
            for (int j = 0; j < 4; ++j) {
                int idx = base + tid + j * TPB;
                v[j] = (idx < q1) ? rp4[idx] : make_float4(-9.f, -9.f, -9.f, -9.f);
            }
#pragma unroll
            for (int j = 0; j < 4; ++j) {
                float xs[4] = {v[j].x, v[j].y, v[j].z, v[j].w};
#pragma unroll
                for (int c = 0; c < 4; ++c) {
                    float x = xs[c];
                    bool q = x > tau;
                    unsigned msk = __ballot_sync(0xffffffffu, q);
                    int off = wcnt + __popc(msk & lmlt);
                    if (q && off < WCAP) wstage[off] = x;
                    wcnt += __popc(msk);
                }
            }
            int i = (q1 << 2) + tid;
            float x = (i < c1) ? rp[i] : -9.f;
            bool qq = x > tau;
            unsigned msk = __ballot_sync(0xffffffffu, qq);
            int off = wcnt + __popc(msk & lmlt);
            if (qq && off < WCAP) wstage[off] = x;
            wcnt += __popc(msk);
        }
    } else {
        // generic scalar path (unaligned T); correctness over speed
        const int nr = c0 + ((c1 - c0 + TPB - 1) / TPB) * TPB;
        for (int i = c0 + tid; i < nr; i += TPB) {
            float x = (i < c1) ? rp[i] : -9.f;
            bool q = x > tau;
            unsigned msk = __ballot_sync(0xffffffffu, q);
            int off = wcnt + __popc(msk & lmlt);
            if (q && off < WCAP) wstage[off] = x;
            wcnt += __popc(msk);
        }
    }

    if (lane == 0) {
        s_wc[wid] = wcnt;
        if (wcnt > WCAP) g_ovf[row] = 1;     // only possible if chunkLen > NWARP*WCAP
    }
    __syncthreads();

    if (tid == 0) {
        int tot = 0;
#pragma unroll
        for (int j = 0; j < NWARP; ++j) { s_pre[j] = tot; tot += s_wc[j]; }
        int gbase = atomicAdd(&g_widx[row], tot);
        if (gbase + tot > BUFCAP) g_ovf[row] = 1;
        s_gbase = gbase;
    }
    __syncthreads();
    {
        const int cnt  = min(s_wc[wid], WCAP);
        const int base = s_gbase + s_pre[wid];
        for (int i = lane; i < cnt; i += 32) {
            int d = base + i;
            if (d < BUFCAP) g_wbuf[row][d] = wstage[i];
        }
    }
    __threadfence();
    __syncthreads();
    if (tid == 0) s_isfin = (atomicAdd(&g_rowdone[row], 1) == Sact - 1) ? 1 : 0;
    __syncthreads();
    if (!s_isfin) return;

    // ================= finisher: last slice block completes the row =================
    __threadfence();

    if (tid == 0) {
        int m  = g_widx[row];
        int ok = (!g_ovf[row]) && (m >= k) && (m <= BUFCAP);
        s_m = m; s_ok = ok; s_donef = 0; s_status = 1;
        s_thr = 0.5f; s_CU = 0; s_SU = 0.0f;
    }
    __syncthreads();

    const int ok = s_ok;

    if (ok) {
        const int m = s_m;
        for (int i = tid; i < m; i += TPB) s_sel[i] = g_wbuf[row][i];
        __syncthreads();

        // ---- 1-pass bucket select: k-th largest among m candidates in (tau, 1) ----
        const float Ls = fmaxf(tau, 0.0f);
        const float Us = 1.0f;
        const float scale = (float)NB / (Us - Ls);

        for (int j = tid; j < NB; j += TPB) s_hist[j] = 0;
        __syncthreads();
        for (int i = tid; i < m; i += TPB) {
            float x = s_sel[i];
            int bi = (int)((Us - x) * scale);
            bi = bi < 0 ? 0 : (bi > NB - 1 ? NB - 1 : bi);
            atomicAdd(&s_hist[bi], 1);
        }
        __syncthreads();
        if (tid < NCO) {
            int t = 0;
#pragma unroll
            for (int j = 0; j < 16; ++j) t += s_hist[tid * 16 + j];
            s_coarse[tid] = t;
        }
        __syncthreads();
        if (tid == 0) {
            int cum = 0, cb = 0;
            while (cb < NCO - 1 && cum + s_coarse[cb] < k) { cum += s_coarse[cb]; ++cb; }
            int b = cb * 16;
            while (b < NB - 1 && cum + s_hist[b] < k) { cum += s_hist[b]; ++b; }
            s_b = b; s_above = cum; s_nb = 0;
        }
        __syncthreads();

        const int b = s_b;
        float sa = 0.0f;
        for (int i = tid; i < m; i += TPB) {
            float x = s_sel[i];
            int bi = (int)((Us - x) * scale);
            bi = bi < 0 ? 0 : (bi > NB - 1 ? NB - 1 : bi);
            if (bi < b) sa += x;
            else if (bi == b) {
                int p = atomicAdd(&s_nb, 1);
                if (p < BBCAP) s_bb[p] = x;
            }
        }
        sa = warpRedF(sa);
        if (lane == 0) s_rf[wid] = sa;
        __syncthreads();

        const int nb = s_nb;
        if (nb <= BBCAP) {
            const int kk2 = k - s_above;     // 1..nb by construction
            if (tid < nb) {
                float xv = s_bb[tid]; int r = 0;
                for (int j = 0; j < nb; ++j) {
                    float y = s_bb[j];
                    r += (y > xv) || (y == xv && j < tid);
                }
                s_rank[tid] = r;
            }
            __syncthreads();
            float c = (tid < nb && s_rank[tid] < kk2) ? s_bb[tid] : 0.0f;
            c = warpRedF(c);
            if (lane == 0) s_rf2[wid] = c;
            __syncthreads();
            if (tid == 0) {
                float SA = 0.0f, SS = 0.0f;
#pragma unroll
                for (int j = 0; j < NWARP; ++j) { SA += s_rf[j]; SS += s_rf2[j]; }
                float topk = SA + SS;        // exactly k elements summed
                float vl   = topk / (float)k;
                float lab  = label[row];
                g_rowloss[row] = -(lab * logf(vl) + (1.0f - lab) * log1pf(-vl));
                s_donef = 1;
            }
            __syncthreads();
        }
        // nb > BBCAP (heavy ties): fall through to radix select on s_sel below
    }

    if (!s_donef) {
        if (!ok) {
            // ---- deterministic fallback: full-row bisection (scalar; never-taken path) ----
            float gL = 0.0f, gU = 1.0f;
            bool  tiemode = false;
            if (tid == 0) {
                s_Lb = 0.0f; s_Ub = 0.5f;
                s_status = 0; s_m = 0; s_thr = 0.5f; s_CU = 0; s_SU = 0.0f;
            }
            const int nr = ((n + TPB - 1) / TPB) * TPB;

            for (int iter = 0; iter < 64; ++iter) {
                __syncthreads();
                const float Lb = s_Lb, Ub = s_Ub;
                if (tid == 0) s_nc = 0;
                __syncthreads();

                int cu = 0, cl = 0; float su = 0.0f;
                for (int i = tid; i < nr; i += TPB) {
                    float x = (i < n) ? rp[i] : -9.f;
                    bool gtU = x > Ub, gtL = x > Lb;
                    cl += gtL;
                    if (gtU) { cu++; su += x; }
                    else if (gtL) {
                        int p = atomicAdd(&s_nc, 1);
                        if (p < SELCAP) s_sel[p] = x;
                    }
                }
                cu = warpRedI(cu); cl = warpRedI(cl); su = warpRedF(su);
                if (lane == 0) { s_ri[wid] = cu; s_ri2[wid] = cl; s_rf[wid] = su; }
                __syncthreads();

                if (tid == 0) {
                    int CU = 0, CL = 0; float SU = 0.0f;
                    for (int j = 0; j < NWARP; ++j) { CU += s_ri[j]; CL += s_ri2[j]; SU += s_rf[j]; }
                    if (tiemode) {
                        s_status = 2; s_CU = CU; s_SU = SU; s_m = 0; s_thr = Ub;
                    } else {
                        bool done = false;
                        if (CU < k && CL >= k) {
                            int mm = CL - CU;
                            if (mm <= SELCAP) {
                                s_status = 1; s_CU = CU; s_SU = SU; s_m = mm;
                                done = true;
                            } else { gL = Lb; gU = Ub; }
                        } else if (CU >= k) {
                            gL = Ub;
                        } else {
                            gU = Lb;
                        }
                        if (!done) {
                            if (__float_as_uint(gU) - __float_as_uint(gL) <= 1u) {
                                tiemode = true; s_Lb = gU; s_Ub = gU;
                            } else {
                                float mid = 0.5f * (gL + gU);
                                if (!(mid > gL && mid < gU))
                                    mid = __uint_as_float((__float_as_uint(gL) + __float_as_uint(gU)) >> 1);
                                s_Lb = gL; s_Ub = mid;
                            }
                        }
                    }
                }
                __syncthreads();
                if (s_status != 0) break;
            }
            __syncthreads();
        }

        const int st = s_status;
        const int m2 = s_m;

        if (st == 1) {
            // exact 8-bit radix select among m2 positive floats in s_sel
            if (tid == 0) { s_prefix = 0u; s_kk = k - s_CU; }
            for (int pos = 24; pos >= 0; pos -= 8) {
                __syncthreads();
                for (int j = tid; j < 256; j += TPB) s_hist[j] = 0;
                __syncthreads();
                const unsigned pref  = s_prefix;
                const unsigned pmask = (pos == 24) ? 0u : (0xffffffffu << (pos + 8));
                for (int i = tid; i < m2; i += TPB) {
                    unsigned v = __float_as_uint(s_sel[i]);
                    if ((v & pmask) == pref)
                        atomicAdd(&s_hist[(v >> pos) & 255], 1);
                }
                __syncthreads();
                if (tid == 0) {
                    int kk = s_kk;
                    int c = 0, d = 255;
                    for (; d >= 0; --d) { c += s_hist[d]; if (c >= kk) break; }
                    if (d < 0) d = 0;
                    s_kk = kk - (c - s_hist[d]);
                    s_prefix = pref | ((unsigned)d << (unsigned)pos);
                }
            }
            __syncthreads();
            if (tid == 0) s_thr = __uint_as_float(s_prefix);
            __syncthreads();
        }

        // tie-corrected top-k sum with exact threshold
        const float thr = s_thr;
        float sg = 0.0f; int cg = 0;
        for (int i = tid; i < m2; i += TPB) {
            float x = s_sel[i];
            if (x > thr) { sg += x; cg++; }
        }
        sg = warpRedF(sg); cg = warpRedI(cg);
        if (lane == 0) { s_rf[wid] = sg; s_ri[wid] = cg; }
        __syncthreads();
        if (tid == 0) {
            float SG = 0.0f; int CG = 0;
            for (int j = 0; j < NWARP; ++j) { SG += s_rf[j]; CG += s_ri[j]; }
            float topk = s_SU + SG + (float)(k - s_CU - CG) * thr;
            float vl   = topk / (float)k;
            float lab  = label[row];
            g_rowloss[row] = -(lab * logf(vl) + (1.0f - lab) * log1pf(-vl));
        }
        __syncthreads();
    }

    // reset per-row scratch for next graph replay
    if (tid == 0) { g_widx[row] = 0; g_ovf[row] = 0; g_rowdone[row] = 0; }
    __threadfence();
    __syncthreads();
    if (tid == 0) s_lastB = (atomicAdd(&g_done, 1u) == (unsigned)(B - 1)) ? 1 : 0;
    __syncthreads();
    if (s_lastB) {
        __threadfence();
        float v = 0.0f;
        for (int i = tid; i < B; i += TPB) v += g_rowloss[i];
        v = warpRedF(v);
        if (lane == 0) s_rf[wid] = v;
        __syncthreads();
        if (tid == 0) {
            float t = 0.0f;
            for (int j = 0; j < NWARP; ++j) t += s_rf[j];
            out[0] = t / (float)B;
            g_done = 0;
        }
    }
}

extern "C" void kernel_launch(void* const* d_in, const int* in_sizes, int n_in,
                              void* d_out, int out_size) {
    const float* scores = (const float*)d_in[0];
    const float* label  = (const float*)d_in[1];
    const int*   seqlen = (const int*)d_in[2];
    int B = in_sizes[1];
    if (B > MAXB) B = MAXB;
    int T = in_sizes[0] / B;

    int S = (T + CHUNK - 1) / CHUNK;
    if (S < 1) S = 1;
    int chunkLen = CHUNK;
    if (S > MAXS) {                       // very long rows: widen chunks (overflow -> fallback)
        S = MAXS;
        chunkLen = (((T + S - 1) / S) + 15) & ~15;
    }

    fused_kernel<<<B * S, TPB>>>(scores, label, seqlen, T, B, S, chunkLen, (float*)d_out);
}

// round 6
// speedup vs baseline: 1.6226x; 1.0057x over previous
#include <cuda_runtime.h>
#include <math.h>

#define TPB 256
#define NWARP 8
#define WTCAP 16               // private slots per thread = elems/thread per chunk
#define SELCAP 4096            // WTCAP * TPB; stage + select buffer
#define BUFCAP 4096            // global per-row candidate buffer
#define CHUNK 4096             // elements per slice block
#define NB 512                 // select buckets
#define NCO 32                 // coarse bins (NB/16)
#define BBCAP 64               // boundary-bucket capacity
#define MAXB 2048
#define MAXS 16
#define SMALLN 2048            // rows this short are captured whole (tau = -1)

__device__ float    g_rowloss[MAXB];
__device__ unsigned g_done;                 // zero-init; reset by last block each launch
__device__ float    g_wbuf[MAXB][BUFCAP];   // per-row candidates (> tau)
__device__ int      g_widx[MAXB];           // per-row candidate count (reset by finisher)
__device__ int      g_ovf[MAXB];            // per-row overflow flag   (reset by finisher)
__device__ int      g_rowdone[MAXB];        // per-row slice-done count (reset by finisher)

__device__ __forceinline__ float warpRedF(float v) {
#pragma unroll
    for (int o = 16; o > 0; o >>= 1) v += __shfl_down_sync(0xffffffffu, v, o);
    return v;
}
__device__ __forceinline__ int warpRedI(int v) {
#pragma unroll
    for (int o = 16; o > 0; o >>= 1) v += __shfl_down_sync(0xffffffffu, v, o);
    return v;
}

// single capture threshold: below the k-th order statistic whp (uniform scores)
__device__ __forceinline__ float row_tau(int n, int k) {
    if (n <= SMALLN) return -1.0f;          // capture everything
    float fn = (float)n, fk = (float)k;
    return fmaxf(0.0f, 1.0f - fk / fn - 10.0f * sqrtf(fk) / fn);
}

__global__ __launch_bounds__(TPB) void fused_kernel(
    const float* __restrict__ scores,
    const float* __restrict__ label,
    const int*   __restrict__ seqlen,
    int T, int B, int S, int chunkLen,
    float* __restrict__ out)
{
    __shared__ float s_sel[SELCAP];          // private strided stage, then select buffer
    __shared__ int   s_hist[NB];
    __shared__ int   s_coarse[NCO];
    __shared__ float s_bb[BBCAP];
    __shared__ int   s_rank[BBCAP];
    __shared__ float s_rf[NWARP], s_rf2[NWARP];
    __shared__ int   s_ri[NWARP], s_ri2[NWARP];
    __shared__ int   s_wc[NWARP], s_pre[NWARP];
    __shared__ int   s_gbase, s_isfin, s_lastB, s_donef;
    __shared__ int   s_m, s_ok, s_b, s_above, s_nb, s_nc;
    __shared__ float s_thr, s_Lb, s_Ub, s_SU;
    __shared__ int   s_status, s_kk, s_CU;
    __shared__ unsigned s_prefix;

    const int gid  = blockIdx.x;
    const int row  = gid / S;
    const int sl   = gid - row * S;
    const int tid  = threadIdx.x;
    const int lane = tid & 31;
    const int wid  = tid >> 5;

    const int n  = seqlen[row];
    const int c0 = sl * chunkLen;
    if (c0 >= n) return;                     // inactive slice
    const int Sact = (n + chunkLen - 1) / chunkLen;
    const int k    = (n >> 4) + 1;           // seqlen//16 + 1
    const float tau = row_tau(n, k);

    const float* rp = scores + (size_t)row * (size_t)T;
    const int c1 = min(c0 + chunkLen, n);

    // ------------- stream: 3-instr predicated private-slot filter -------------
    int slot = tid;                           // element index into s_sel; slot j at j*TPB+tid

    if (((T & 3) == 0) && chunkLen == CHUNK) {
        const float4* rp4 = (const float4*)rp;
        const int q0 = c0 >> 2, q1 = c1 >> 2;
        int base = q0;
        // unguarded full groups: 4 independent LDG.128 per thread
        for (; base + 4 * TPB <= q1; base += 4 * TPB) {
            float4 v[4];
#pragma unroll
            for (int j = 0; j < 4; ++j) v[j] = rp4[base + tid + j * TPB];
#pragma unroll
            for (int j = 0; j < 4; ++j) {
                float xs[4] = {v[j].x, v[j].y, v[j].z, v[j].w};
#pragma unroll
                for (int c = 0; c < 4; ++c) {
                    float x = xs[c];
                    if (x > tau) { s_sel[slot] = x; slot += TPB; }   // never overflows
                }
            }
        }
        // guarded remainder group + scalar tail (block-uniform condition)
        if (base < q1 || (q1 << 2) < c1) {
            float4 v[4];
#pragma unroll
            for (int j = 0; j < 4; ++j) {
                int idx = base + tid + j * TPB;
                v[j] = (idx < q1) ? rp4[idx] : make_float4(-9.f, -9.f, -9.f, -9.f);
            }
#pragma unroll
            for (int j = 0; j < 4; ++j) {
                float xs[4] = {v[j].x, v[j].y, v[j].z, v[j].w};
#pragma unroll
                for (int c = 0; c < 4; ++c) {
                    float x = xs[c];
                    if (x > tau) { s_sel[slot] = x; slot += TPB; }
                }
            }
            int i = (q1 << 2) + tid;
            if (i < c1) {
                float x = rp[i];
                if (x > tau) { s_sel[slot] = x; slot += TPB; }
            }
        }
    } else {
        // generic path (unaligned T or widened chunks): guarded slots
        for (int i = c0 + tid; i < c1; i += TPB) {
            float x = rp[i];
            if (x > tau) {
                if (slot < SELCAP) s_sel[slot] = x;
                slot += TPB;
            }
        }
    }

    int cnt = (slot - tid) >> 8;              // candidates this thread captured
    if (cnt > WTCAP) g_ovf[row] = 1;          // only reachable on widened chunks

    // ------------- block prefix sum of per-thread counts -------------
    int inc = cnt;
#pragma unroll
    for (int o = 1; o < 32; o <<= 1) {
        int t = __shfl_up_sync(0xffffffffu, inc, o);
        if (lane >= o) inc += t;
    }
    const int excl = inc - cnt;
    if (lane == 31) s_wc[wid] = inc;          // warp total
    __syncthreads();
    if (tid == 0) {
        int tot = 0;
#pragma unroll
        for (int j = 0; j < NWARP; ++j) { s_pre[j] = tot; tot += s_wc[j]; }
        int gbase = atomicAdd(&g_widx[row], tot);
        if (gbase + tot > BUFCAP) g_ovf[row] = 1;
        s_gbase = gbase;
    }
    __syncthreads();

    // ------------- flush private slots to per-row global buffer -------------
    {
        const int dst = s_gbase + s_pre[wid] + excl;
        const int cc  = min(cnt, WTCAP);
        for (int j = 0; j < cc; ++j) {
            int d = dst + j;
            if (d < BUFCAP) g_wbuf[row][d] = s_sel[j * TPB + tid];
        }
    }
    __threadfence();
    __syncthreads();
    if (tid == 0) s_isfin = (atomicAdd(&g_rowdone[row], 1) == Sact - 1) ? 1 : 0;
    __syncthreads();
    if (!s_isfin) return;

    // ================= finisher: last slice block completes the row =================
    __threadfence();

    if (tid == 0) {
        int m  = g_widx[row];
        int ok = (!g_ovf[row]) && (m >= k) && (m <= BUFCAP);
        s_m = m; s_ok = ok; s_donef = 0; s_status = 1;
        s_thr = 0.5f; s_CU = 0; s_SU = 0.0f;
    }
    __syncthreads();

    const int ok = s_ok;

    if (ok) {
        const int m = s_m;
        for (int i = tid; i < m; i += TPB) s_sel[i] = g_wbuf[row][i];
        __syncthreads();

        // ---- 1-pass bucket select: k-th largest among m candidates in (tau, 1) ----
        const float Ls = fmaxf(tau, 0.0f);
        const float Us = 1.0f;
        const float scale = (float)NB / (Us - Ls);

        for (int j = tid; j < NB; j += TPB) s_hist[j] = 0;
        __syncthreads();
        for (int i = tid; i < m; i += TPB) {
            float x = s_sel[i];
            int bi = (int)((Us - x) * scale);
            bi = bi < 0 ? 0 : (bi > NB - 1 ? NB - 1 : bi);
            atomicAdd(&s_hist[bi], 1);
        }
        __syncthreads();
        if (tid < NCO) {
            int t = 0;
#pragma unroll
            for (int j = 0; j < 16; ++j) t += s_hist[tid * 16 + j];
            s_coarse[tid] = t;
        }
        __syncthreads();
        if (tid == 0) {
            int cum = 0, cb = 0;
            while (cb < NCO - 1 && cum + s_coarse[cb] < k) { cum += s_coarse[cb]; ++cb; }
            int b = cb * 16;
            while (b < NB - 1 && cum + s_hist[b] < k) { cum += s_hist[b]; ++b; }
            s_b = b; s_above = cum; s_nb = 0;
        }
        __syncthreads();

        const int b = s_b;
        float sa = 0.0f;
        for (int i = tid; i < m; i += TPB) {
            float x = s_sel[i];
            int bi = (int)((Us - x) * scale);
            bi = bi < 0 ? 0 : (bi > NB - 1 ? NB - 1 : bi);
            if (bi < b) sa += x;
            else if (bi == b) {
                int p = atomicAdd(&s_nb, 1);
                if (p < BBCAP) s_bb[p] = x;
            }
        }
        sa = warpRedF(sa);
        if (lane == 0) s_rf[wid] = sa;
        __syncthreads();

        const int nb = s_nb;
        if (nb <= BBCAP) {
            const int kk2 = k - s_above;      // 1..nb by construction
            if (tid < nb) {
                float xv = s_bb[tid]; int r = 0;
                for (int j = 0; j < nb; ++j) {
                    float y = s_bb[j];
                    r += (y > xv) || (y == xv && j < tid);
                }
                s_rank[tid] = r;
            }
            __syncthreads();
            float c = (tid < nb && s_rank[tid] < kk2) ? s_bb[tid] : 0.0f;
            c = warpRedF(c);
            if (lane == 0) s_rf2[wid] = c;
            __syncthreads();
            if (tid == 0) {
                float SA = 0.0f, SS = 0.0f;
#pragma unroll
                for (int j = 0; j < NWARP; ++j) { SA += s_rf[j]; SS += s_rf2[j]; }
                float topk = SA + SS;         // exactly k elements summed
                float vl   = topk / (float)k;
                float lab  = label[row];
                g_rowloss[row] = -(lab * logf(vl) + (1.0f - lab) * log1pf(-vl));
                s_donef = 1;
            }
            __syncthreads();
        }
        // nb > BBCAP (heavy ties): fall through to radix select on s_sel below
    }

    if (!s_donef) {
        if (!ok) {
            // ---- deterministic fallback: full-row bisection (scalar; never-taken path) ----
            float gL = 0.0f, gU = 1.0f;
            bool  tiemode = false;
            if (tid == 0) {
                s_Lb = 0.0f; s_Ub = 0.5f;
                s_status = 0; s_m = 0; s_thr = 0.5f; s_CU = 0; s_SU = 0.0f;
            }
            const int nr = ((n + TPB - 1) / TPB) * TPB;

            for (int iter = 0; iter < 64; ++iter) {
                __syncthreads();
                const float Lb = s_Lb, Ub = s_Ub;
                if (tid == 0) s_nc = 0;
                __syncthreads();

                int cu = 0, cl = 0; float su = 0.0f;
                for (int i = tid; i < nr; i += TPB) {
                    float x = (i < n) ? rp[i] : -9.f;
                    bool gtU = x > Ub, gtL = x > Lb;
                    cl += gtL;
                    if (gtU) { cu++; su += x; }
                    else if (gtL) {
                        int p = atomicAdd(&s_nc, 1);
                        if (p < SELCAP) s_sel[p] = x;
                    }
                }
                cu = warpRedI(cu); cl = warpRedI(cl); su = warpRedF(su);
                if (lane == 0) { s_ri[wid] = cu; s_ri2[wid] = cl; s_rf[wid] = su; }
                __syncthreads();

                if (tid == 0) {
                    int CU = 0, CL = 0; float SU = 0.0f;
                    for (int j = 0; j < NWARP; ++j) { CU += s_ri[j]; CL += s_ri2[j]; SU += s_rf[j]; }
                    if (tiemode) {
                        s_status = 2; s_CU = CU; s_SU = SU; s_m = 0; s_thr = Ub;
                    } else {
                        bool done = false;
                        if (CU < k && CL >= k) {
                            int mm = CL - CU;
                            if (mm <= SELCAP) {
                                s_status = 1; s_CU = CU; s_SU = SU; s_m = mm;
                                done = true;
                            } else { gL = Lb; gU = Ub; }
                        } else if (CU >= k) {
                            gL = Ub;
                        } else {
                            gU = Lb;
                        }
                        if (!done) {
                            if (__float_as_uint(gU) - __float_as_uint(gL) <= 1u) {
                                tiemode = true; s_Lb = gU; s_Ub = gU;
                            } else {
                                float mid = 0.5f * (gL + gU);
                                if (!(mid > gL && mid < gU))
                                    mid = __uint_as_float((__float_as_uint(gL) + __float_as_uint(gU)) >> 1);
                                s_Lb = gL; s_Ub = mid;
                            }
                        }
                    }
                }
                __syncthreads();
                if (s_status != 0) break;
            }
            __syncthreads();
        }

        const int st = s_status;
        const int m2 = s_m;

        if (st == 1) {
            // exact 8-bit radix select among m2 positive floats in s_sel
            if (tid == 0) { s_prefix = 0u; s_kk = k - s_CU; }
            for (int pos = 24; pos >= 0; pos -= 8) {
                __syncthreads();
                for (int j = tid; j < 256; j += TPB) s_hist[j] = 0;
                __syncthreads();
                const unsigned pref  = s_prefix;
                const unsigned pmask = (pos == 24) ? 0u : (0xffffffffu << (pos + 8));
                for (int i = tid; i < m2; i += TPB) {
                    unsigned v = __float_as_uint(s_sel[i]);
                    if ((v & pmask) == pref)
                        atomicAdd(&s_hist[(v >> pos) & 255], 1);
                }
                __syncthreads();
                if (tid == 0) {
                    int kk = s_kk;
                    int c = 0, d = 255;
                    for (; d >= 0; --d) { c += s_hist[d]; if (c >= kk) break; }
                    if (d < 0) d = 0;
                    s_kk = kk - (c - s_hist[d]);
                    s_prefix = pref | ((unsigned)d << (unsigned)pos);
                }
            }
            __syncthreads();
            if (tid == 0) s_thr = __uint_as_float(s_prefix);
            __syncthreads();
        }

        // tie-corrected top-k sum with exact threshold
        const float thr = s_thr;
        float sg = 0.0f; int cg = 0;
        for (int i = tid; i < m2; i += TPB) {
            float x = s_sel[i];
            if (x > thr) { sg += x; cg++; }
        }
        sg = warpRedF(sg); cg = warpRedI(cg);
        if (lane == 0) { s_rf[wid] = sg; s_ri[wid] = cg; }
        __syncthreads();
        if (tid == 0) {
            float SG = 0.0f; int CG = 0;
            for (int j = 0; j < NWARP; ++j) { SG += s_rf[j]; CG += s_ri[j]; }
            float topk = s_SU + SG + (float)(k - s_CU - CG) * thr;
            float vl   = topk / (float)k;
            float lab  = label[row];
            g_rowloss[row] = -(lab * logf(vl) + (1.0f - lab) * log1pf(-vl));
        }
        __syncthreads();
    }

    // reset per-row scratch for next graph replay
    if (tid == 0) { g_widx[row] = 0; g_ovf[row] = 0; g_rowdone[row] = 0; }
    __threadfence();
    __syncthreads();
    if (tid == 0) s_lastB = (atomicAdd(&g_done, 1u) == (unsigned)(B - 1)) ? 1 : 0;
    __syncthreads();
    if (s_lastB) {
        __threadfence();
        float v = 0.0f;
        for (int i = tid; i < B; i += TPB) v += g_rowloss[i];
        v = warpRedF(v);
        if (lane == 0) s_rf[wid] = v;
        __syncthreads();
        if (tid == 0) {
            float t = 0.0f;
            for (int j = 0; j < NWARP; ++j) t += s_rf[j];
            out[0] = t / (float)B;
            g_done = 0;
        }
    }
}

extern "C" void kernel_launch(void* const* d_in, const int* in_sizes, int n_in,
                              void* d_out, int out_size) {
    const float* scores = (const float*)d_in[0];
    const float* label  = (const float*)d_in[1];
    const int*   seqlen = (const int*)d_in[2];
    int B = in_sizes[1];
    if (B > MAXB) B = MAXB;
    int T = in_sizes[0] / B;

    int S = (T + CHUNK - 1) / CHUNK;
    if (S < 1) S = 1;
    int chunkLen = CHUNK;
    if (S > MAXS) {                       // very long rows: widen chunks (overflow -> fallback)
        S = MAXS;
        chunkLen = (((T + S - 1) / S) + 15) & ~15;
    }

    fused_kernel<<<B * S, TPB>>>(scores, label, seqlen, T, B, S, chunkLen, (float*)d_out);
}

// round 7
// speedup vs baseline: 2.5530x; 1.5734x over previous
#include <cuda_runtime.h>
#include <math.h>

#define TPB 256
#define NWARP 8
#define WTCAP 28               // private slots per thread (mean ~10, +6 sigma)
#define SLIM (WTCAP * TPB)     // 7168; dump slot at SLIM
#define SELCAP SLIM            // fallback linear candidate buffer capacity
#define NB 512                 // select buckets
#define NCO 32                 // coarse bins (NB/16)
#define BBCAP 64               // boundary-bucket capacity
#define MAXB 4096
#define SMALLN 2048            // rows this short are captured whole (tau = -1)

__device__ float    g_rowloss[MAXB];
__device__ unsigned g_done;    // zero-init; reset by last block each launch

__device__ __forceinline__ float warpRedF(float v) {
#pragma unroll
    for (int o = 16; o > 0; o >>= 1) v += __shfl_down_sync(0xffffffffu, v, o);
    return v;
}
__device__ __forceinline__ int warpRedI(int v) {
#pragma unroll
    for (int o = 16; o > 0; o >>= 1) v += __shfl_down_sync(0xffffffffu, v, o);
    return v;
}

// capture threshold: below the k-th order statistic whp (uniform scores)
__device__ __forceinline__ float row_tau(int n, int k) {
    if (n <= SMALLN) return -1.0f;          // capture everything
    float fn = (float)n, fk = (float)k;
    return fmaxf(0.0f, 1.0f - fk / fn - 10.0f * sqrtf(fk) / fn);
}

__global__ __launch_bounds__(TPB, 7) void topk_bce_kernel(
    const float* __restrict__ scores,
    const float* __restrict__ label,
    const int*   __restrict__ seqlen,
    int T, int B,
    float* __restrict__ out)
{
    __shared__ float s_stage[SLIM + 32];     // strided slots + dump pad (also fallback buffer)
    __shared__ int   s_hist[NB];
    __shared__ int   s_coarse[NCO];
    __shared__ float s_bb[BBCAP];
    __shared__ int   s_rank[BBCAP];
    __shared__ float s_rf[NWARP], s_rf2[NWARP];
    __shared__ int   s_ri[NWARP], s_ri2[NWARP];
    __shared__ int   s_ovf, s_m, s_ok, s_b, s_above, s_nb, s_nc;
    __shared__ float s_thr, s_Lb, s_Ub, s_SU;
    __shared__ int   s_status, s_kk, s_CU, s_donef, s_lastB;
    __shared__ unsigned s_prefix;

    const int row  = blockIdx.x;
    const int tid  = threadIdx.x;
    const int lane = tid & 31;
    const int wid  = tid >> 5;

    const int n = seqlen[row];
    const int k = (n >> 4) + 1;              // seqlen//16 + 1, 1 <= k <= n
    const float tau = row_tau(n, k);
    const float* rp = scores + (size_t)row * (size_t)T;

    if (tid == 0) s_ovf = 0;
    __syncthreads();

    // ---------------- stream whole row: predicated private-slot filter ----------------
    int slot = tid;                           // slot j lives at j*TPB + tid

    if ((T & 3) == 0) {
        const float4* rp4 = (const float4*)rp;
        const int nv = n >> 2;
        int base = 0;
        for (; base + 4 * TPB <= nv; base += 4 * TPB) {   // MLP=4, unguarded
            float4 v[4];
#pragma unroll
            for (int j = 0; j < 4; ++j) v[j] = rp4[base + tid + j * TPB];
#pragma unroll
            for (int j = 0; j < 4; ++j) {
                float xs[4] = {v[j].x, v[j].y, v[j].z, v[j].w};
#pragma unroll
                for (int c = 0; c < 4; ++c) {
                    float x = xs[c];
                    if (x > tau) {
                        s_stage[slot < SLIM ? slot : SLIM] = x;
                        slot += TPB;
                    }
                }
            }
        }
        if (base < nv || (nv << 2) < n) {     // guarded remainder + scalar tail
            float4 v[4];
#pragma unroll
            for (int j = 0; j < 4; ++j) {
                int idx = base + tid + j * TPB;
                v[j] = (idx < nv) ? rp4[idx] : make_float4(-9.f, -9.f, -9.f, -9.f);
            }
#pragma unroll
            for (int j = 0; j < 4; ++j) {
                float xs[4] = {v[j].x, v[j].y, v[j].z, v[j].w};
#pragma unroll
                for (int c = 0; c < 4; ++c) {
                    float x = xs[c];
                    if (x > tau) {
                        s_stage[slot < SLIM ? slot : SLIM] = x;
                        slot += TPB;
                    }
                }
            }
            int i = (nv << 2) + tid;
            if (i < n) {
                float x = rp[i];
                if (x > tau) {
                    s_stage[slot < SLIM ? slot : SLIM] = x;
                    slot += TPB;
                }
            }
        }
    } else {
        for (int i = tid; i < n; i += TPB) {  // generic path (unaligned T)
            float x = rp[i];
            if (x > tau) {
                s_stage[slot < SLIM ? slot : SLIM] = x;
                slot += TPB;
            }
        }
    }

    int cnt = (slot - tid) >> 8;              // candidates this thread captured
    if (cnt > WTCAP) s_ovf = 1;               // lost data -> fallback

    // total m
    int mm = warpRedI(cnt);
    if (lane == 0) s_ri[wid] = mm;
    __syncthreads();
    if (tid == 0) {
        int m = 0;
#pragma unroll
        for (int j = 0; j < NWARP; ++j) m += s_ri[j];
        s_m = m;
        s_ok = (!s_ovf) && (m >= k);
        s_donef = 0; s_status = 1; s_thr = 0.5f; s_CU = 0; s_SU = 0.0f;
    }
    __syncthreads();

    const int ok = s_ok;
    const int cc = min(cnt, WTCAP);

    // ---------------- fast path: 1-pass bucket select over private slots ----------------
    if (ok) {
        const float Ls = fmaxf(tau, 0.0f);
        const float Us = 1.0f;
        const float scale = (float)NB / (Us - Ls);

        for (int j = tid; j < NB; j += TPB) s_hist[j] = 0;
        __syncthreads();
        for (int j = 0; j < cc; ++j) {
            float x = s_stage[j * TPB + tid];
            int bi = (int)((Us - x) * scale);
            bi = bi < 0 ? 0 : (bi > NB - 1 ? NB - 1 : bi);
            atomicAdd(&s_hist[bi], 1);
        }
        __syncthreads();
        if (tid < NCO) {
            int t = 0;
#pragma unroll
            for (int j = 0; j < 16; ++j) t += s_hist[tid * 16 + j];
            s_coarse[tid] = t;
        }
        __syncthreads();
        if (tid == 0) {
            int cum = 0, cb = 0;
            while (cb < NCO - 1 && cum + s_coarse[cb] < k) { cum += s_coarse[cb]; ++cb; }
            int b = cb * 16;
            while (b < NB - 1 && cum + s_hist[b] < k) { cum += s_hist[b]; ++b; }
            s_b = b; s_above = cum; s_nb = 0;
        }
        __syncthreads();

        const int b = s_b;
        float sa = 0.0f;
        for (int j = 0; j < cc; ++j) {
            float x = s_stage[j * TPB + tid];
            int bi = (int)((Us - x) * scale);
            bi = bi < 0 ? 0 : (bi > NB - 1 ? NB - 1 : bi);
            if (bi < b) sa += x;
            else if (bi == b) {
                int p = atomicAdd(&s_nb, 1);
                if (p < BBCAP) s_bb[p] = x;
            }
        }
        sa = warpRedF(sa);
        if (lane == 0) s_rf[wid] = sa;
        __syncthreads();

        const int nb = s_nb;
        if (nb <= BBCAP) {
            const int kk2 = k - s_above;      // 1..nb by construction
            if (tid < nb) {
                float xv = s_bb[tid]; int r = 0;
                for (int j = 0; j < nb; ++j) {
                    float y = s_bb[j];
                    r += (y > xv) || (y == xv && j < tid);  // ties: equal values, sum-invariant
                }
                s_rank[tid] = r;
            }
            __syncthreads();
            float c = (tid < nb && s_rank[tid] < kk2) ? s_bb[tid] : 0.0f;
            c = warpRedF(c);
            if (lane == 0) s_rf2[wid] = c;
            __syncthreads();
            if (tid == 0) {
                float SA = 0.0f, SS = 0.0f;
#pragma unroll
                for (int j = 0; j < NWARP; ++j) { SA += s_rf[j]; SS += s_rf2[j]; }
                float topk = SA + SS;         // exactly k elements summed
                float vl   = topk / (float)k;
                float lab  = label[row];
                g_rowloss[row] = -(lab * logf(vl) + (1.0f - lab) * log1pf(-vl));
                s_donef = 1;
            }
            __syncthreads();
        }
        // nb > BBCAP (pathological ties): fall through to bisection fallback
    }

    if (!s_donef) {
        // ---------- deterministic fallback: full-row bisection from gmem ----------
        {
            float gL = 0.0f, gU = 1.0f;
            bool  tiemode = false;
            if (tid == 0) {
                s_Lb = 0.0f; s_Ub = 0.5f;
                s_status = 0; s_m = 0; s_thr = 0.5f; s_CU = 0; s_SU = 0.0f;
            }
            const int nr = ((n + TPB - 1) / TPB) * TPB;

            for (int iter = 0; iter < 64; ++iter) {
                __syncthreads();
                const float Lb = s_Lb, Ub = s_Ub;
                if (tid == 0) s_nc = 0;
                __syncthreads();

                int cu = 0, cl = 0; float su = 0.0f;
                for (int i = tid; i < nr; i += TPB) {
                    float x = (i < n) ? rp[i] : -9.f;
                    bool gtU = x > Ub, gtL = x > Lb;
                    cl += gtL;
                    if (gtU) { cu++; su += x; }
                    else if (gtL) {
                        int p = atomicAdd(&s_nc, 1);
                        if (p < SELCAP) s_stage[p] = x;
                    }
                }
                cu = warpRedI(cu); cl = warpRedI(cl); su = warpRedF(su);
                if (lane == 0) { s_ri[wid] = cu; s_ri2[wid] = cl; s_rf[wid] = su; }
                __syncthreads();

                if (tid == 0) {
                    int CU = 0, CL = 0; float SU = 0.0f;
                    for (int j = 0; j < NWARP; ++j) { CU += s_ri[j]; CL += s_ri2[j]; SU += s_rf[j]; }
                    if (tiemode) {
                        s_status = 2; s_CU = CU; s_SU = SU; s_m = 0; s_thr = Ub;
                    } else {
                        bool done = false;
                        if (CU < k && CL >= k) {
                            int m2 = CL - CU;
                            if (m2 <= SELCAP) {
                                s_status = 1; s_CU = CU; s_SU = SU; s_m = m2;
                                done = true;
                            } else { gL = Lb; gU = Ub; }
                        } else if (CU >= k) {
                            gL = Ub;
                        } else {
                            gU = Lb;
                        }
                        if (!done) {
                            if (__float_as_uint(gU) - __float_as_uint(gL) <= 1u) {
                                tiemode = true; s_Lb = gU; s_Ub = gU;
                            } else {
                                float mid = 0.5f * (gL + gU);
                                if (!(mid > gL && mid < gU))
                                    mid = __uint_as_float((__float_as_uint(gL) + __float_as_uint(gU)) >> 1);
                                s_Lb = gL; s_Ub = mid;
                            }
                        }
                    }
                }
                __syncthreads();
                if (s_status != 0) break;
            }
            __syncthreads();
        }

        const int st = s_status;
        const int m2 = s_m;

        if (st == 1) {
            // exact 8-bit radix select among m2 positive floats in s_stage (linear)
            if (tid == 0) { s_prefix = 0u; s_kk = k - s_CU; }
            for (int pos = 24; pos >= 0; pos -= 8) {
                __syncthreads();
                for (int j = tid; j < 256; j += TPB) s_hist[j] = 0;
                __syncthreads();
                const unsigned pref  = s_prefix;
                const unsigned pmask = (pos == 24) ? 0u : (0xffffffffu << (pos + 8));
                for (int i = tid; i < m2; i += TPB) {
                    unsigned v = __float_as_uint(s_stage[i]);
                    if ((v & pmask) == pref)
                        atomicAdd(&s_hist[(v >> pos) & 255], 1);
                }
                __syncthreads();
                if (tid == 0) {
                    int kk = s_kk;
                    int c = 0, d = 255;
                    for (; d >= 0; --d) { c += s_hist[d]; if (c >= kk) break; }
                    if (d < 0) d = 0;
                    s_kk = kk - (c - s_hist[d]);
                    s_prefix = pref | ((unsigned)d << (unsigned)pos);
                }
            }
            __syncthreads();
            if (tid == 0) s_thr = __uint_as_float(s_prefix);
            __syncthreads();
        }

        // tie-corrected top-k sum with exact threshold
        const float thr = s_thr;
        float sg = 0.0f; int cg = 0;
        for (int i = tid; i < m2; i += TPB) {
            float x = s_stage[i];
            if (x > thr) { sg += x; cg++; }
        }
        sg = warpRedF(sg); cg = warpRedI(cg);
        if (lane == 0) { s_rf[wid] = sg; s_ri[wid] = cg; }
        __syncthreads();
        if (tid == 0) {
            float SG = 0.0f; int CG = 0;
            for (int j = 0; j < NWARP; ++j) { SG += s_rf[j]; CG += s_ri[j]; }
            float topk = s_SU + SG + (float)(k - s_CU - CG) * thr;
            float vl   = topk / (float)k;
            float lab  = label[row];
            g_rowloss[row] = -(lab * logf(vl) + (1.0f - lab) * log1pf(-vl));
        }
        __syncthreads();
    }

    // ---------------- last-block-done: final scalar reduction ----------------
    __threadfence();
    if (tid == 0) s_lastB = (atomicAdd(&g_done, 1u) == (unsigned)(B - 1)) ? 1 : 0;
    __syncthreads();
    if (s_lastB) {
        __threadfence();
        float v = 0.0f;
        for (int i = tid; i < B; i += TPB) v += g_rowloss[i];
        v = warpRedF(v);
        if (lane == 0) s_rf[wid] = v;
        __syncthreads();
        if (tid == 0) {
            float t = 0.0f;
            for (int j = 0; j < NWARP; ++j) t += s_rf[j];
            out[0] = t / (float)B;
            g_done = 0;
        }
    }
}

extern "C" void kernel_launch(void* const* d_in, const int* in_sizes, int n_in,
                              void* d_out, int out_size) {
    const float* scores = (const float*)d_in[0];
    const float* label  = (const float*)d_in[1];
    const int*   seqlen = (const int*)d_in[2];
    int B = in_sizes[1];
    if (B > MAXB) B = MAXB;
    int T = in_sizes[0] / B;

    topk_bce_kernel<<<B, TPB>>>(scores, label, seqlen, T, B, (float*)d_out);
}